// round 5
// baseline (speedup 1.0000x reference)
#include <cuda_runtime.h>

#define NU 200000
#define NI 100000
#define DIM 64
#define NE 3200000

// ---------------- scratch (static __device__, no allocation) ----------------
__device__ int   g_u_cnt[NU];
__device__ int   g_i_cnt[NI];
__device__ int   g_u_off[NU + 1];
__device__ int   g_i_off[NI + 1];
__device__ int   g_u_cur[NU];
__device__ int   g_i_cur[NI];
__device__ int   g_u_bsum[1024];
__device__ int   g_i_bsum[1024];
__device__ int   g_cols_u[NE];
__device__ float g_vals_u[NE];
__device__ int   g_cols_i[NE];
__device__ float g_vals_i[NE];
__device__ __align__(16) float g_hu[(size_t)NU * DIM];
__device__ __align__(16) float g_hi[(size_t)NI * DIM];

// ---------------- CSR build ----------------
__global__ void zero_cnt_kernel(int* __restrict__ u_cnt, int* __restrict__ i_cnt) {
    int i = blockIdx.x * 256 + threadIdx.x;
    if (i < NU) u_cnt[i] = 0;
    if (i < NI) i_cnt[i] = 0;
}

__global__ void hist_kernel(const int* __restrict__ u_idx, const int* __restrict__ i_idx,
                            int* __restrict__ u_cnt, int* __restrict__ i_cnt) {
    int e = blockIdx.x * 256 + threadIdx.x;
    if (e >= NE) return;
    atomicAdd(&u_cnt[u_idx[e]], 1);
    atomicAdd(&i_cnt[i_idx[e]], 1);
}

__global__ void scanA_kernel(const int* __restrict__ cnt, int* __restrict__ exc,
                             int* __restrict__ bsum, int n) {
    __shared__ int s[256];
    int tid = threadIdx.x;
    int i = blockIdx.x * 256 + tid;
    int v = (i < n) ? cnt[i] : 0;
    s[tid] = v;
    __syncthreads();
    for (int o = 1; o < 256; o <<= 1) {
        int t = (tid >= o) ? s[tid - o] : 0;
        __syncthreads();
        s[tid] += t;
        __syncthreads();
    }
    if (i < n) exc[i] = s[tid] - v;        // exclusive
    if (tid == 255) bsum[blockIdx.x] = s[tid];
}

__global__ void scanB_kernel(int* __restrict__ bsum, int nb) {
    __shared__ int s[1024];
    int tid = threadIdx.x;
    int v = (tid < nb) ? bsum[tid] : 0;
    s[tid] = v;
    __syncthreads();
    for (int o = 1; o < 1024; o <<= 1) {
        int t = (tid >= o) ? s[tid - o] : 0;
        __syncthreads();
        s[tid] += t;
        __syncthreads();
    }
    if (tid < nb) bsum[tid] = s[tid] - v;  // exclusive
}

__global__ void scanC_kernel(int* __restrict__ exc, const int* __restrict__ bsum,
                             int* __restrict__ cur, int n, int total) {
    int i = blockIdx.x * 256 + threadIdx.x;
    if (i < n) {
        int v = exc[i] + bsum[i >> 8];
        exc[i] = v;
        cur[i] = v;
    }
    if (i == 0) exc[n] = total;
}

__global__ void scatter_kernel(const int* __restrict__ u_idx, const int* __restrict__ i_idx,
                               const float* __restrict__ w_u2i, const float* __restrict__ w_i2u,
                               int* __restrict__ u_cur, int* __restrict__ i_cur,
                               int* __restrict__ cols_u, float* __restrict__ vals_u,
                               int* __restrict__ cols_i, float* __restrict__ vals_i) {
    int e = blockIdx.x * 256 + threadIdx.x;
    if (e >= NE) return;
    int u = u_idx[e];
    int it = i_idx[e];
    int pu = atomicAdd(&u_cur[u], 1);
    cols_u[pu] = it;
    vals_u[pu] = w_u2i[e];
    int pi = atomicAdd(&i_cur[it], 1);
    cols_i[pi] = u;
    vals_i[pi] = w_i2u[e];
}

// ---------------- fused layer ----------------
// Persistent. Per warp: gather 8 rows (concat x staged in smem, pre-duplicated
// for f32x2), then dense [128->64] GEMM with j-pair-packed W (fma.rn.f32x2),
// ReLU + L2 normalize, store.
//
// Dynamic smem layout (96 KB):
//   WB[2048] float4 : WB[(s*2+h)*32 + l] = {W[2l][kk0], W[2l+1][kk0],
//                                           W[2l][kk0+1], W[2l+1][kk0+1]},
//                     kk0 = h*64 + 2*s,  s in [0,32), h in {0,1}, l in [0,32)
//   xd[4096] float4 : per warp 512 entries. xd[w*512 + (r*32+s)*2 + 0] =
//                     {x[2s],x[2s],x[2s+1],x[2s+1]} (self half),
//                     ... + 1 = neigh half {x[64+2s],...}
#define FMA2(Y, A, B) asm("fma.rn.f32x2 %0, %1, %2, %0;" : "+l"(Y) : "l"(A), "l"(B))

__global__ void __launch_bounds__(256) layer_kernel(
    const float* __restrict__ h_self, const float* __restrict__ h_other,
    const int* __restrict__ roff, const int* __restrict__ cols,
    const float* __restrict__ vals, const float* __restrict__ W,
    float* __restrict__ out, int R)
{
    extern __shared__ float4 smem4[];
    float4* WB = smem4;            // 2048 float4 = 32 KB
    float4* xd = smem4 + 2048;     // 4096 float4 = 64 KB

    // fill WB once per block (coalesced enough; runs once)
    for (int t = threadIdx.x; t < 2048; t += 256) {
        int l = t & 31;
        int h = (t >> 5) & 1;
        int s = t >> 6;
        int kk0 = h * 64 + 2 * s;
        int j0 = 2 * l;
        WB[t] = make_float4(W[j0 * 128 + kk0],     W[(j0 + 1) * 128 + kk0],
                            W[j0 * 128 + kk0 + 1], W[(j0 + 1) * 128 + kk0 + 1]);
    }
    __syncthreads();

    int warp = threadIdx.x >> 5;
    int lane = threadIdx.x & 31;
    float4* myxd = xd + warp * 512;
    const ulonglong2* myxdu = (const ulonglong2*)myxd;
    const ulonglong2* WBu = (const ulonglong2*)WB;

    const float2* hs_ptr = (const float2*)h_self;
    const float2* ho_ptr = (const float2*)h_other;

    int gw = blockIdx.x * 8 + warp;          // global warp id
    int nw = gridDim.x * 8;

    for (int base = gw * 8; base < R; base += nw * 8) {
        // -------- gather phase: 8 rows, stage duplicated x into smem --------
        #pragma unroll 1
        for (int r = 0; r < 8; r++) {
            int row = base + r;              // R % 8 == 0 -> always valid
            float2 hs = hs_ptr[(size_t)row * 32 + lane];
            float ax = 0.f, ay = 0.f;
            int e = roff[row];
            int end = roff[row + 1];
            for (; e + 4 <= end; e += 4) {
                int c0 = cols[e], c1 = cols[e + 1], c2 = cols[e + 2], c3 = cols[e + 3];
                float w0 = vals[e], w1 = vals[e + 1], w2 = vals[e + 2], w3 = vals[e + 3];
                float2 v0 = ho_ptr[(size_t)c0 * 32 + lane];
                float2 v1 = ho_ptr[(size_t)c1 * 32 + lane];
                float2 v2 = ho_ptr[(size_t)c2 * 32 + lane];
                float2 v3 = ho_ptr[(size_t)c3 * 32 + lane];
                ax += w0 * v0.x + w1 * v1.x + w2 * v2.x + w3 * v3.x;
                ay += w0 * v0.y + w1 * v1.y + w2 * v2.y + w3 * v3.y;
            }
            for (; e < end; e++) {
                int c = cols[e];
                float w = vals[e];
                float2 v = ho_ptr[(size_t)c * 32 + lane];
                ax += w * v.x;
                ay += w * v.y;
            }
            float4* dst = myxd + (r * 32 + lane) * 2;
            dst[0] = make_float4(hs.x, hs.x, hs.y, hs.y);
            dst[1] = make_float4(ax, ax, ay, ay);
        }
        __syncwarp();

        // -------- dense phase: y(j-pair) = sum_k W[j][k] x[k], f32x2 packed --------
        unsigned long long Y[8];
        #pragma unroll
        for (int r = 0; r < 8; r++) Y[r] = 0ULL;

        #pragma unroll 4
        for (int s = 0; s < 32; s++) {
            ulonglong2 w0 = WBu[(s * 2 + 0) * 32 + lane];   // k = 2s, 2s+1
            ulonglong2 w1 = WBu[(s * 2 + 1) * 32 + lane];   // k = 64+2s, 65+2s
            #pragma unroll
            for (int r = 0; r < 8; r++) {
                ulonglong2 xa = myxdu[(r * 32 + s) * 2 + 0];
                ulonglong2 xb = myxdu[(r * 32 + s) * 2 + 1];
                FMA2(Y[r], xa.x, w0.x);
                FMA2(Y[r], xa.y, w0.y);
                FMA2(Y[r], xb.x, w1.x);
                FMA2(Y[r], xb.y, w1.y);
            }
        }

        // -------- finalize: ReLU + L2 norm + store --------
        #pragma unroll
        for (int r = 0; r < 8; r++) {
            float y0, y1;
            asm("mov.b64 {%0, %1}, %2;" : "=f"(y0), "=f"(y1) : "l"(Y[r]));
            y0 = fmaxf(y0, 0.f);
            y1 = fmaxf(y1, 0.f);
            float ss = y0 * y0 + y1 * y1;
            #pragma unroll
            for (int o = 16; o; o >>= 1) ss += __shfl_xor_sync(0xffffffffu, ss, o);
            float inv = 1.0f / fmaxf(sqrtf(ss), 1e-12f);
            ((float2*)out)[(size_t)(base + r) * 32 + lane] = make_float2(y0 * inv, y1 * inv);
        }
        __syncwarp();
    }
}

// ---------------- launch ----------------
extern "C" void kernel_launch(void* const* d_in, const int* in_sizes, int n_in,
                              void* d_out, int out_size) {
    const float* user_emb = (const float*)d_in[0];
    const float* item_emb = (const float*)d_in[1];
    const float* Wu       = (const float*)d_in[2];   // [2,64,128]
    const float* Wi       = (const float*)d_in[3];
    const int*   u_idx    = (const int*)d_in[4];
    const int*   i_idx    = (const int*)d_in[5];
    const float* w_u2i    = (const float*)d_in[6];
    const float* w_i2u    = (const float*)d_in[7];
    float* out = (float*)d_out;

    void* p;
    int *u_cnt, *i_cnt, *u_off, *i_off, *u_cur, *i_cur, *u_bsum, *i_bsum, *cols_u, *cols_i;
    float *vals_u, *vals_i, *hu, *hi;
    cudaGetSymbolAddress(&p, g_u_cnt);  u_cnt  = (int*)p;
    cudaGetSymbolAddress(&p, g_i_cnt);  i_cnt  = (int*)p;
    cudaGetSymbolAddress(&p, g_u_off);  u_off  = (int*)p;
    cudaGetSymbolAddress(&p, g_i_off);  i_off  = (int*)p;
    cudaGetSymbolAddress(&p, g_u_cur);  u_cur  = (int*)p;
    cudaGetSymbolAddress(&p, g_i_cur);  i_cur  = (int*)p;
    cudaGetSymbolAddress(&p, g_u_bsum); u_bsum = (int*)p;
    cudaGetSymbolAddress(&p, g_i_bsum); i_bsum = (int*)p;
    cudaGetSymbolAddress(&p, g_cols_u); cols_u = (int*)p;
    cudaGetSymbolAddress(&p, g_cols_i); cols_i = (int*)p;
    cudaGetSymbolAddress(&p, g_vals_u); vals_u = (float*)p;
    cudaGetSymbolAddress(&p, g_vals_i); vals_i = (float*)p;
    cudaGetSymbolAddress(&p, g_hu);     hu     = (float*)p;
    cudaGetSymbolAddress(&p, g_hi);     hi     = (float*)p;

    const int EB  = (NE + 255) / 256;        // 12500
    const int UB  = (NU + 255) / 256;        // 782
    const int IB  = (NI + 255) / 256;        // 391

    // CSR build (both directions)
    zero_cnt_kernel<<<UB, 256>>>(u_cnt, i_cnt);
    hist_kernel<<<EB, 256>>>(u_idx, i_idx, u_cnt, i_cnt);
    scanA_kernel<<<UB, 256>>>(u_cnt, u_off, u_bsum, NU);
    scanA_kernel<<<IB, 256>>>(i_cnt, i_off, i_bsum, NI);
    scanB_kernel<<<1, 1024>>>(u_bsum, UB);
    scanB_kernel<<<1, 1024>>>(i_bsum, IB);
    scanC_kernel<<<UB, 256>>>(u_off, u_bsum, u_cur, NU, NE);
    scanC_kernel<<<IB, 256>>>(i_off, i_bsum, i_cur, NI, NE);
    scatter_kernel<<<EB, 256>>>(u_idx, i_idx, w_u2i, w_i2u,
                                u_cur, i_cur, cols_u, vals_u, cols_i, vals_i);

    // persistent layer kernels: 2 blocks/SM at 96 KB dynamic smem
    const int SMEM = 98304;
    static int attr_done = 0;
    if (!attr_done) {
        cudaFuncSetAttribute(layer_kernel, cudaFuncAttributeMaxDynamicSharedMemorySize, SMEM);
        attr_done = 1;
    }
    const int PG = 152 * 2;   // 304 blocks, 8 warps each

    layer_kernel<<<PG, 256, SMEM>>>(user_emb, item_emb, u_off, cols_u, vals_u,
                                    Wu, hu, NU);
    layer_kernel<<<PG, 256, SMEM>>>(item_emb, user_emb, i_off, cols_i, vals_i,
                                    Wi, hi, NI);
    layer_kernel<<<PG, 256, SMEM>>>(hu, hi, u_off, cols_u, vals_u,
                                    Wu + 64 * 128, out, NU);
    layer_kernel<<<PG, 256, SMEM>>>(hi, hu, i_off, cols_i, vals_i,
                                    Wi + 64 * 128, out + (size_t)NU * DIM, NI);
}